// round 3
// baseline (speedup 1.0000x reference)
#include <cuda_runtime.h>
#include <cuda_bf16.h>

// Problem constants
#define B      2
#define S      2048
#define DM     1024
#define H      16
#define DH     64
#define BH     (B*H)          // 32
#define MTOT   (B*S)          // 4096
#define IGNORE_VAL (-1e5f)

// Scratch (global device arrays; no allocations allowed)
__device__ float g_Q[B*H*S*DH];   // [b,h,s,e]
__device__ float g_K[B*H*S*DH];
__device__ float g_V[B*H*S*DH];
__device__ float g_Z[B*S*DM];     // [b,s, h*64+e]

// ---------------------------------------------------------------------------
// Kernel 1: fused QKV projection.
// x:[4096,1024] @ W[h]:[1024,64] (+bias) -> g_{Q,K,V}[b,h,s,e]
// grid: (MTOT/64, 48)  (48 = 3 mats * 16 heads), block 256.
// ---------------------------------------------------------------------------
__global__ void qkv_gemm(const float* __restrict__ x,
                         const float* __restrict__ Wq,
                         const float* __restrict__ Wk,
                         const float* __restrict__ Wv,
                         const float* __restrict__ bq,
                         const float* __restrict__ bk,
                         const float* __restrict__ bv) {
    __shared__ float As[32][65];  // [k][m], padded
    __shared__ float Bs[32][64];  // [k][n]

    const int tid = threadIdx.x;
    const int tx  = tid & 15;
    const int ty  = tid >> 4;
    const int m0  = blockIdx.x * 64;
    const int nt  = blockIdx.y;          // 0..47
    const int mat = nt >> 4;             // 0=Q 1=K 2=V
    const int h   = nt & 15;

    const float* W    = (mat == 0) ? Wq : (mat == 1 ? Wk : Wv);
    const float* bias = (mat == 0) ? bq : (mat == 1 ? bk : bv);
    const float* Wh   = W + h * (DM * DH);

    float acc[4][4] = {};

    for (int k0 = 0; k0 < DM; k0 += 32) {
        #pragma unroll
        for (int i = 0; i < 8; i++) {
            int idx = tid + i * 256;             // 2048 elems
            int k = idx & 31, m = idx >> 5;
            As[k][m] = x[(m0 + m) * DM + k0 + k];
        }
        #pragma unroll
        for (int i = 0; i < 8; i++) {
            int idx = tid + i * 256;
            int n = idx & 63, k = idx >> 6;
            Bs[k][n] = Wh[(k0 + k) * DH + n];
        }
        __syncthreads();
        #pragma unroll
        for (int k = 0; k < 32; k++) {
            float a0 = As[k][ty];
            float a1 = As[k][ty + 16];
            float a2 = As[k][ty + 32];
            float a3 = As[k][ty + 48];
            float4 b = *(const float4*)&Bs[k][tx * 4];
            acc[0][0] += a0 * b.x; acc[0][1] += a0 * b.y; acc[0][2] += a0 * b.z; acc[0][3] += a0 * b.w;
            acc[1][0] += a1 * b.x; acc[1][1] += a1 * b.y; acc[1][2] += a1 * b.z; acc[1][3] += a1 * b.w;
            acc[2][0] += a2 * b.x; acc[2][1] += a2 * b.y; acc[2][2] += a2 * b.z; acc[2][3] += a2 * b.w;
            acc[3][0] += a3 * b.x; acc[3][1] += a3 * b.y; acc[3][2] += a3 * b.z; acc[3][3] += a3 * b.w;
        }
        __syncthreads();
    }

    float* dst = (mat == 0) ? g_Q : (mat == 1 ? g_K : g_V);
    #pragma unroll
    for (int i = 0; i < 4; i++) {
        int gm = m0 + ty + 16 * i;
        int b  = gm >> 11;         // /2048
        int s  = gm & 2047;
        #pragma unroll
        for (int j = 0; j < 4; j++) {
            int e = tx * 4 + j;
            dst[((b * H + h) * S + s) * DH + e] = acc[i][j] + bias[h * DH + e];
        }
    }
}

// ---------------------------------------------------------------------------
// Kernel 2: causal flash attention, fp32 online softmax.
// grid: (S/64 = 32 q-tiles, BH = 32), block 256. smem = exactly 48KB static.
// ---------------------------------------------------------------------------
__global__ void attn_kernel() {
    __shared__ float Qs[64 * 64];   // [q][e] natural
    __shared__ float KP[64 * 64];   // phase1: K^T as [e][k^swz]; phase2: P as [q][k]
    __shared__ float Vs[64 * 64];   // [k][d] natural

    const int tid = threadIdx.x;
    const int tx  = tid & 15;
    const int ty  = tid >> 4;
    const int bh  = blockIdx.y;
    const int qt  = (int)gridDim.x - 1 - (int)blockIdx.x;  // big tiles launch first

    const float* Qp = g_Q + (size_t)bh * S * DH + qt * 64 * DH;
    const float* Kp = g_K + (size_t)bh * S * DH;
    const float* Vp = g_V + (size_t)bh * S * DH;

    #pragma unroll
    for (int i = 0; i < 16; i++) {
        int idx = tid + i * 256;
        Qs[idx] = Qp[idx];          // [q][e], fully coalesced
    }

    float m_i[4], l_i[4], acc[4][4] = {};
    #pragma unroll
    for (int i = 0; i < 4; i++) { m_i[i] = -1e30f; l_i[i] = 0.f; }

    for (int kt = 0; kt <= qt; kt++) {
        const float* Kt = Kp + kt * 64 * DH;
        const float* Vt = Vp + kt * 64 * DH;
        #pragma unroll
        for (int i = 0; i < 16; i++) {
            int idx = tid + i * 256;
            int e = idx & 63, k = idx >> 6;
            KP[e * 64 + (k ^ (e & 31))] = Kt[k * 64 + e];   // transposed, XOR-swizzled
            Vs[idx] = Vt[idx];
        }
        __syncthreads();

        // S = Q K^T
        float s[4][4] = {};
        #pragma unroll
        for (int e = 0; e < 64; e++) {
            float a0 = Qs[ty * 64 + e];
            float a1 = Qs[(ty + 16) * 64 + e];
            float a2 = Qs[(ty + 32) * 64 + e];
            float a3 = Qs[(ty + 48) * 64 + e];
            const int sw = e & 31;
            float b0 = KP[e * 64 + ((tx * 4 + 0) ^ sw)];
            float b1 = KP[e * 64 + ((tx * 4 + 1) ^ sw)];
            float b2 = KP[e * 64 + ((tx * 4 + 2) ^ sw)];
            float b3 = KP[e * 64 + ((tx * 4 + 3) ^ sw)];
            s[0][0] += a0 * b0; s[0][1] += a0 * b1; s[0][2] += a0 * b2; s[0][3] += a0 * b3;
            s[1][0] += a1 * b0; s[1][1] += a1 * b1; s[1][2] += a1 * b2; s[1][3] += a1 * b3;
            s[2][0] += a2 * b0; s[2][1] += a2 * b1; s[2][2] += a2 * b2; s[2][3] += a2 * b3;
            s[3][0] += a3 * b0; s[3][1] += a3 * b1; s[3][2] += a3 * b2; s[3][3] += a3 * b3;
        }

        // scale + causal mask (diagonal tile only)
        #pragma unroll
        for (int i = 0; i < 4; i++)
            #pragma unroll
            for (int j = 0; j < 4; j++)
                s[i][j] *= 0.125f;
        if (kt == qt) {
            #pragma unroll
            for (int i = 0; i < 4; i++)
                #pragma unroll
                for (int j = 0; j < 4; j++)
                    if (tx * 4 + j > ty + 16 * i) s[i][j] = IGNORE_VAL;
        }

        // online softmax stats (reduce across 16 lanes sharing the same rows)
        float mx[4];
        #pragma unroll
        for (int i = 0; i < 4; i++)
            mx[i] = fmaxf(fmaxf(s[i][0], s[i][1]), fmaxf(s[i][2], s[i][3]));
        #pragma unroll
        for (int o = 8; o > 0; o >>= 1)
            #pragma unroll
            for (int i = 0; i < 4; i++)
                mx[i] = fmaxf(mx[i], __shfl_xor_sync(0xffffffffu, mx[i], o));

        float alpha[4];
        #pragma unroll
        for (int i = 0; i < 4; i++) {
            float mnew = fmaxf(m_i[i], mx[i]);
            alpha[i] = __expf(m_i[i] - mnew);
            m_i[i] = mnew;
        }
        #pragma unroll
        for (int i = 0; i < 4; i++)
            #pragma unroll
            for (int j = 0; j < 4; j++)
                s[i][j] = __expf(s[i][j] - m_i[i]);

        float rs[4];
        #pragma unroll
        for (int i = 0; i < 4; i++)
            rs[i] = (s[i][0] + s[i][1]) + (s[i][2] + s[i][3]);
        #pragma unroll
        for (int o = 8; o > 0; o >>= 1)
            #pragma unroll
            for (int i = 0; i < 4; i++)
                rs[i] += __shfl_xor_sync(0xffffffffu, rs[i], o);
        #pragma unroll
        for (int i = 0; i < 4; i++)
            l_i[i] = l_i[i] * alpha[i] + rs[i];

        #pragma unroll
        for (int i = 0; i < 4; i++)
            #pragma unroll
            for (int j = 0; j < 4; j++)
                acc[i][j] *= alpha[i];

        __syncthreads();   // everyone done reading K from KP

        // P -> KP as [q][k]
        #pragma unroll
        for (int i = 0; i < 4; i++)
            #pragma unroll
            for (int j = 0; j < 4; j++)
                KP[(ty + 16 * i) * 64 + tx * 4 + j] = s[i][j];
        __syncthreads();

        // acc += P V
        #pragma unroll
        for (int k = 0; k < 64; k++) {
            float a0 = KP[ty * 64 + k];
            float a1 = KP[(ty + 16) * 64 + k];
            float a2 = KP[(ty + 32) * 64 + k];
            float a3 = KP[(ty + 48) * 64 + k];
            float4 b = *(const float4*)&Vs[k * 64 + tx * 4];
            acc[0][0] += a0 * b.x; acc[0][1] += a0 * b.y; acc[0][2] += a0 * b.z; acc[0][3] += a0 * b.w;
            acc[1][0] += a1 * b.x; acc[1][1] += a1 * b.y; acc[1][2] += a1 * b.z; acc[1][3] += a1 * b.w;
            acc[2][0] += a2 * b.x; acc[2][1] += a2 * b.y; acc[2][2] += a2 * b.z; acc[2][3] += a2 * b.w;
            acc[3][0] += a3 * b.x; acc[3][1] += a3 * b.y; acc[3][2] += a3 * b.z; acc[3][3] += a3 * b.w;
        }
        __syncthreads();   // before next tile's loads overwrite KP/Vs
    }

    // epilogue: Z[b, q, h*64+d] = acc / l
    const int b = bh >> 4, h = bh & 15;
    #pragma unroll
    for (int i = 0; i < 4; i++) {
        float inv = 1.f / l_i[i];
        int q = qt * 64 + ty + 16 * i;
        float* zrow = g_Z + ((size_t)(b * S + q)) * DM + h * DH + tx * 4;
        #pragma unroll
        for (int j = 0; j < 4; j++)
            zrow[j] = acc[i][j] * inv;
    }
}

// ---------------------------------------------------------------------------
// Kernel 3: output projection. g_Z:[4096,1024] @ W_O_flat:[1024,1024] + b_O
// grid: (64, 16), block 256.
// ---------------------------------------------------------------------------
__global__ void oproj_gemm(const float* __restrict__ Wo,
                           const float* __restrict__ bo,
                           float* __restrict__ out) {
    __shared__ float As[32][65];
    __shared__ float Bs[32][64];

    const int tid = threadIdx.x;
    const int tx  = tid & 15;
    const int ty  = tid >> 4;
    const int m0  = blockIdx.x * 64;
    const int n0  = blockIdx.y * 64;

    float acc[4][4] = {};

    for (int k0 = 0; k0 < DM; k0 += 32) {
        #pragma unroll
        for (int i = 0; i < 8; i++) {
            int idx = tid + i * 256;
            int k = idx & 31, m = idx >> 5;
            As[k][m] = g_Z[(m0 + m) * DM + k0 + k];
        }
        #pragma unroll
        for (int i = 0; i < 8; i++) {
            int idx = tid + i * 256;
            int n = idx & 63, k = idx >> 6;
            Bs[k][n] = Wo[(k0 + k) * DM + n0 + n];
        }
        __syncthreads();
        #pragma unroll
        for (int k = 0; k < 32; k++) {
            float a0 = As[k][ty];
            float a1 = As[k][ty + 16];
            float a2 = As[k][ty + 32];
            float a3 = As[k][ty + 48];
            float4 b = *(const float4*)&Bs[k][tx * 4];
            acc[0][0] += a0 * b.x; acc[0][1] += a0 * b.y; acc[0][2] += a0 * b.z; acc[0][3] += a0 * b.w;
            acc[1][0] += a1 * b.x; acc[1][1] += a1 * b.y; acc[1][2] += a1 * b.z; acc[1][3] += a1 * b.w;
            acc[2][0] += a2 * b.x; acc[2][1] += a2 * b.y; acc[2][2] += a2 * b.z; acc[2][3] += a2 * b.w;
            acc[3][0] += a3 * b.x; acc[3][1] += a3 * b.y; acc[3][2] += a3 * b.z; acc[3][3] += a3 * b.w;
        }
        __syncthreads();
    }

    #pragma unroll
    for (int i = 0; i < 4; i++) {
        int m = m0 + ty + 16 * i;
        #pragma unroll
        for (int j = 0; j < 4; j++) {
            int n = n0 + tx * 4 + j;
            out[(size_t)m * DM + n] = acc[i][j] + bo[n];
        }
    }
}

// ---------------------------------------------------------------------------
extern "C" void kernel_launch(void* const* d_in, const int* in_sizes, int n_in,
                              void* d_out, int out_size) {
    const float* x   = (const float*)d_in[0];
    const float* W_Q = (const float*)d_in[1];
    const float* W_K = (const float*)d_in[2];
    const float* W_V = (const float*)d_in[3];
    const float* W_O = (const float*)d_in[4];
    const float* b_Q = (const float*)d_in[5];
    const float* b_K = (const float*)d_in[6];
    const float* b_V = (const float*)d_in[7];
    const float* b_O = (const float*)d_in[8];
    float* out = (float*)d_out;

    dim3 g1(MTOT / 64, 48);
    qkv_gemm<<<g1, 256>>>(x, W_Q, W_K, W_V, b_Q, b_K, b_V);

    dim3 g2(S / 64, BH);
    attn_kernel<<<g2, 256>>>();

    dim3 g3(MTOT / 64, DM / 64);
    oproj_gemm<<<g3, 256>>>(W_O, b_O, out);
}

// round 13
// speedup vs baseline: 1.3943x; 1.3943x over previous
#include <cuda_runtime.h>
#include <cuda_bf16.h>
#include <mma.h>
#include <stdint.h>

using namespace nvcuda;

// Problem constants
#define B      2
#define S      2048
#define DM     1024
#define H      16
#define DH     64
#define BH     (B*H)          // 32
#define MTOT   (B*S)          // 4096
#define NQKV   (3*DM)         // 3072
#define IGNORE_VAL (-1e5f)

// ---------------------------------------------------------------------------
// Global scratch (no allocations allowed). 16B-aligned for vector access.
// NOTE: these are referenced ONLY from device code — never passed as kernel
// arguments from host (that was the R5/R6/R11 bug: host-side address of a
// __device__ variable is garbage).
// ---------------------------------------------------------------------------
__device__ __align__(16) float g_Q[B*H*S*DH];   // [b,h,s,e]
__device__ __align__(16) float g_K[B*H*S*DH];
__device__ __align__(16) float g_V[B*H*S*DH];

__device__ __align__(16) __nv_bfloat16 g_xh[MTOT*DM];   // x split hi/lo, [m][k]
__device__ __align__(16) __nv_bfloat16 g_xl[MTOT*DM];
__device__ __align__(16) __nv_bfloat16 g_wqh[NQKV*DM];  // packed QKV W, [n][k]
__device__ __align__(16) __nv_bfloat16 g_wql[NQKV*DM];
__device__ __align__(16) __nv_bfloat16 g_woh[DM*DM];    // packed O W, [n][k]
__device__ __align__(16) __nv_bfloat16 g_wol[DM*DM];
__device__ __align__(16) __nv_bfloat16 g_zh[MTOT*DM];   // attn out, [m][h*64+e]
__device__ __align__(16) __nv_bfloat16 g_zl[MTOT*DM];

// ---------------------------------------------------------------------------
// Pre-passes: bf16 hi/lo splits + weight packing (globals referenced directly)
// ---------------------------------------------------------------------------
__global__ void split_x_kernel(const float* __restrict__ x) {
    int i = blockIdx.x * 256 + threadIdx.x;
    if (i < MTOT * DM) {
        float v = x[i];
        __nv_bfloat16 hi = __float2bfloat16(v);
        __nv_bfloat16 lo = __float2bfloat16(v - __bfloat162float(hi));
        g_xh[i] = hi; g_xl[i] = lo;
    }
}

// W_{Q,K,V}[h][d][e] -> B operand [n = mat*1024 + h*64 + e][k = d]
__global__ void pack_wqkv_kernel(const float* __restrict__ Wq,
                                 const float* __restrict__ Wk,
                                 const float* __restrict__ Wv) {
    int i = blockIdx.x * 256 + threadIdx.x;
    if (i < NQKV * DM) {
        int n = i >> 10, k = i & 1023;
        int mat = n >> 10, h = (n >> 6) & 15, e = n & 63;
        const float* W = (mat == 0) ? Wq : (mat == 1 ? Wk : Wv);
        float v = W[(h * DM + k) * DH + e];
        __nv_bfloat16 hi = __float2bfloat16(v);
        __nv_bfloat16 lo = __float2bfloat16(v - __bfloat162float(hi));
        g_wqh[i] = hi; g_wql[i] = lo;
    }
}

// W_O[h][e][d] (contig = [k=h*64+e][d]) -> B operand [n=d][k]
__global__ void pack_wo_kernel(const float* __restrict__ Wo) {
    int i = blockIdx.x * 256 + threadIdx.x;
    if (i < DM * DM) {
        int n = i >> 10, k = i & 1023;
        float v = Wo[k * DM + n];
        __nv_bfloat16 hi = __float2bfloat16(v);
        __nv_bfloat16 lo = __float2bfloat16(v - __bfloat162float(hi));
        g_woh[i] = hi; g_wol[i] = lo;
    }
}

// ---------------------------------------------------------------------------
// WMMA GEMM: C[M,N] = A[M,K] * B[N,K]^T, bf16 3-term split, fp32 accum.
// Block 128x128, 8 warps (4Mx2N), warp tile 32x64 = 2x4 wmma 16x16x16 tiles.
// K chunks of 32. Static smem: 4 tiles of 128 x 40 bf16 (80B stride).
// MODE 0: A=g_xh/g_xl, B=g_wqh/g_wql, epilogue -> g_Q/g_K/g_V + bias
// MODE 1: A=g_zh/g_zl, B=g_woh/g_wol, epilogue -> out + b_O
// All scratch pointers resolved in DEVICE code.
// ---------------------------------------------------------------------------
#define LDS_E  40                 // smem row stride in elements
#define TILE_E (128*LDS_E)        // 5120 elements per tile

template<int MODE>
__global__ void __launch_bounds__(256) gemm_wmma(
    const float* __restrict__ bq, const float* __restrict__ bk,
    const float* __restrict__ bv, const float* __restrict__ bo,
    float* __restrict__ out)
{
    __shared__ __align__(16) __nv_bfloat16 sAh[TILE_E];
    __shared__ __align__(16) __nv_bfloat16 sAl[TILE_E];
    __shared__ __align__(16) __nv_bfloat16 sBh[TILE_E];
    __shared__ __align__(16) __nv_bfloat16 sBl[TILE_E];

    // Device-side resolution of scratch arrays (the critical fix)
    const __nv_bfloat16* __restrict__ Ah = (MODE == 0) ? g_xh : g_zh;
    const __nv_bfloat16* __restrict__ Al = (MODE == 0) ? g_xl : g_zl;
    const __nv_bfloat16* __restrict__ Bh = (MODE == 0) ? g_wqh : g_woh;
    const __nv_bfloat16* __restrict__ Bl = (MODE == 0) ? g_wql : g_wol;

    const int tid = threadIdx.x;
    const int wid = tid >> 5;
    const int ln  = tid & 31;
    const int warpM = wid >> 1;          // 0..3
    const int warpN = wid & 1;           // 0..1
    const int m0 = blockIdx.x * 128;
    const int n0 = blockIdx.y * 128;

    wmma::fragment<wmma::accumulator, 16, 16, 16, float> c[2][4];
    #pragma unroll
    for (int mt = 0; mt < 2; mt++)
        #pragma unroll
        for (int nt = 0; nt < 4; nt++)
            wmma::fill_fragment(c[mt][nt], 0.0f);

    for (int ch = 0; ch < 32; ch++) {    // K chunks of 32
        // ---- load 4 tiles of 128x32 bf16 into padded smem (uint4 = 8 bf16) ----
        #pragma unroll
        for (int i = 0; i < 2; i++) {
            int idx = tid + i * 256;     // 0..511
            int row = idx >> 2, sl = idx & 3;
            int se = row * LDS_E + sl * 8;
            size_t ga = (size_t)(m0 + row) * DM + ch * 32 + sl * 8;
            size_t gb = (size_t)(n0 + row) * DM + ch * 32 + sl * 8;
            *(uint4*)(sAh + se) = *(const uint4*)(Ah + ga);
            *(uint4*)(sAl + se) = *(const uint4*)(Al + ga);
            *(uint4*)(sBh + se) = *(const uint4*)(Bh + gb);
            *(uint4*)(sBl + se) = *(const uint4*)(Bl + gb);
        }
        __syncthreads();

        #pragma unroll
        for (int kk = 0; kk < 2; kk++) {   // two k16 steps
            wmma::fragment<wmma::matrix_a, 16, 16, 16, __nv_bfloat16, wmma::row_major> aH[2], aL[2];
            wmma::fragment<wmma::matrix_b, 16, 16, 16, __nv_bfloat16, wmma::col_major> bH[4], bL[4];
            #pragma unroll
            for (int mt = 0; mt < 2; mt++) {
                int off = (warpM * 32 + mt * 16) * LDS_E + kk * 16;
                wmma::load_matrix_sync(aH[mt], sAh + off, LDS_E);
                wmma::load_matrix_sync(aL[mt], sAl + off, LDS_E);
            }
            #pragma unroll
            for (int nt = 0; nt < 4; nt++) {
                int off = (warpN * 64 + nt * 16) * LDS_E + kk * 16;
                wmma::load_matrix_sync(bH[nt], sBh + off, LDS_E);
                wmma::load_matrix_sync(bL[nt], sBl + off, LDS_E);
            }
            #pragma unroll
            for (int mt = 0; mt < 2; mt++) {
                #pragma unroll
                for (int nt = 0; nt < 4; nt++) {
                    wmma::mma_sync(c[mt][nt], aH[mt], bH[nt], c[mt][nt]);
                    wmma::mma_sync(c[mt][nt], aH[mt], bL[nt], c[mt][nt]);
                    wmma::mma_sync(c[mt][nt], aL[mt], bH[nt], c[mt][nt]);
                }
            }
        }
        __syncthreads();
    }

    // ---- epilogue: stage each 16x16 C tile through per-warp smem ----
    float* stage = reinterpret_cast<float*>(sAh) + wid * 256;   // 1KB per warp
    #pragma unroll
    for (int mt = 0; mt < 2; mt++) {
        #pragma unroll
        for (int nt = 0; nt < 4; nt++) {
            wmma::store_matrix_sync(stage, c[mt][nt], 16, wmma::mem_row_major);
            __syncwarp();
            int mb = m0 + warpM * 32 + mt * 16;
            int nb = n0 + warpN * 64 + nt * 16;
            #pragma unroll
            for (int j = 0; j < 8; j++) {
                int idx = ln * 8 + j;           // 0..255
                int r = idx >> 4, cc = idx & 15;
                int m = mb + r, n = nb + cc;
                float v = stage[idx];
                if (MODE == 0) {
                    int bb = m >> 11, s = m & 2047;
                    int mat = n >> 10, h = (n >> 6) & 15, e = n & 63;
                    const float* bias = (mat == 0) ? bq : (mat == 1 ? bk : bv);
                    float* dst = (mat == 0) ? g_Q : (mat == 1 ? g_K : g_V);
                    dst[((size_t)(bb * H + h) * S + s) * DH + e] = v + bias[h * DH + e];
                } else {
                    out[(size_t)m * DM + n] = v + bo[n];
                }
            }
            __syncwarp();
        }
    }
}

// ---------------------------------------------------------------------------
// Causal flash attention, fp32 SIMT online softmax (proven R1 core).
// Epilogue writes Z as bf16 hi/lo for the WMMA O-projection.
// ---------------------------------------------------------------------------
__global__ void attn_kernel() {
    __shared__ float Qs[64 * 64];
    __shared__ float KP[64 * 64];
    __shared__ float Vs[64 * 64];

    const int tid = threadIdx.x;
    const int tx  = tid & 15;
    const int ty  = tid >> 4;
    const int bh  = blockIdx.y;
    const int qt  = (int)gridDim.x - 1 - (int)blockIdx.x;

    const float* Qp = g_Q + (size_t)bh * S * DH + qt * 64 * DH;
    const float* Kp = g_K + (size_t)bh * S * DH;
    const float* Vp = g_V + (size_t)bh * S * DH;

    #pragma unroll
    for (int i = 0; i < 16; i++) {
        int idx = tid + i * 256;
        Qs[idx] = Qp[idx];
    }

    float m_i[4], l_i[4], acc[4][4] = {};
    #pragma unroll
    for (int i = 0; i < 4; i++) { m_i[i] = -1e30f; l_i[i] = 0.f; }

    for (int kt = 0; kt <= qt; kt++) {
        const float* Kt = Kp + kt * 64 * DH;
        const float* Vt = Vp + kt * 64 * DH;
        #pragma unroll
        for (int i = 0; i < 16; i++) {
            int idx = tid + i * 256;
            int e = idx & 63, k = idx >> 6;
            KP[e * 64 + (k ^ (e & 31))] = Kt[k * 64 + e];
            Vs[idx] = Vt[idx];
        }
        __syncthreads();

        float s[4][4] = {};
        #pragma unroll
        for (int e = 0; e < 64; e++) {
            float a0 = Qs[ty * 64 + e];
            float a1 = Qs[(ty + 16) * 64 + e];
            float a2 = Qs[(ty + 32) * 64 + e];
            float a3 = Qs[(ty + 48) * 64 + e];
            const int sw = e & 31;
            float b0 = KP[e * 64 + ((tx * 4 + 0) ^ sw)];
            float b1 = KP[e * 64 + ((tx * 4 + 1) ^ sw)];
            float b2 = KP[e * 64 + ((tx * 4 + 2) ^ sw)];
            float b3 = KP[e * 64 + ((tx * 4 + 3) ^ sw)];
            s[0][0] += a0 * b0; s[0][1] += a0 * b1; s[0][2] += a0 * b2; s[0][3] += a0 * b3;
            s[1][0] += a1 * b0; s[1][1] += a1 * b1; s[1][2] += a1 * b2; s[1][3] += a1 * b3;
            s[2][0] += a2 * b0; s[2][1] += a2 * b1; s[2][2] += a2 * b2; s[2][3] += a2 * b3;
            s[3][0] += a3 * b0; s[3][1] += a3 * b1; s[3][2] += a3 * b2; s[3][3] += a3 * b3;
        }

        #pragma unroll
        for (int i = 0; i < 4; i++)
            #pragma unroll
            for (int j = 0; j < 4; j++)
                s[i][j] *= 0.125f;
        if (kt == qt) {
            #pragma unroll
            for (int i = 0; i < 4; i++)
                #pragma unroll
                for (int j = 0; j < 4; j++)
                    if (tx * 4 + j > ty + 16 * i) s[i][j] = IGNORE_VAL;
        }

        float mx[4];
        #pragma unroll
        for (int i = 0; i < 4; i++)
            mx[i] = fmaxf(fmaxf(s[i][0], s[i][1]), fmaxf(s[i][2], s[i][3]));
        #pragma unroll
        for (int o = 8; o > 0; o >>= 1)
            #pragma unroll
            for (int i = 0; i < 4; i++)
                mx[i] = fmaxf(mx[i], __shfl_xor_sync(0xffffffffu, mx[i], o));

        float alpha[4];
        #pragma unroll
        for (int i = 0; i < 4; i++) {
            float mnew = fmaxf(m_i[i], mx[i]);
            alpha[i] = __expf(m_i[i] - mnew);
            m_i[i] = mnew;
        }
        #pragma unroll
        for (int i = 0; i < 4; i++)
            #pragma unroll
            for (int j = 0; j < 4; j++)
                s[i][j] = __expf(s[i][j] - m_i[i]);

        float rs[4];
        #pragma unroll
        for (int i = 0; i < 4; i++)
            rs[i] = (s[i][0] + s[i][1]) + (s[i][2] + s[i][3]);
        #pragma unroll
        for (int o = 8; o > 0; o >>= 1)
            #pragma unroll
            for (int i = 0; i < 4; i++)
                rs[i] += __shfl_xor_sync(0xffffffffu, rs[i], o);
        #pragma unroll
        for (int i = 0; i < 4; i++)
            l_i[i] = l_i[i] * alpha[i] + rs[i];

        #pragma unroll
        for (int i = 0; i < 4; i++)
            #pragma unroll
            for (int j = 0; j < 4; j++)
                acc[i][j] *= alpha[i];

        __syncthreads();

        #pragma unroll
        for (int i = 0; i < 4; i++)
            #pragma unroll
            for (int j = 0; j < 4; j++)
                KP[(ty + 16 * i) * 64 + tx * 4 + j] = s[i][j];
        __syncthreads();

        #pragma unroll
        for (int k = 0; k < 64; k++) {
            float a0 = KP[ty * 64 + k];
            float a1 = KP[(ty + 16) * 64 + k];
            float a2 = KP[(ty + 32) * 64 + k];
            float a3 = KP[(ty + 48) * 64 + k];
            float4 b = *(const float4*)&Vs[k * 64 + tx * 4];
            acc[0][0] += a0 * b.x; acc[0][1] += a0 * b.y; acc[0][2] += a0 * b.z; acc[0][3] += a0 * b.w;
            acc[1][0] += a1 * b.x; acc[1][1] += a1 * b.y; acc[1][2] += a1 * b.z; acc[1][3] += a1 * b.w;
            acc[2][0] += a2 * b.x; acc[2][1] += a2 * b.y; acc[2][2] += a2 * b.z; acc[2][3] += a2 * b.w;
            acc[3][0] += a3 * b.x; acc[3][1] += a3 * b.y; acc[3][2] += a3 * b.z; acc[3][3] += a3 * b.w;
        }
        __syncthreads();
    }

    // epilogue: Z -> bf16 hi/lo at [b*S+q][h*64+e]
    const int b = bh >> 4, h = bh & 15;
    #pragma unroll
    for (int i = 0; i < 4; i++) {
        float inv = 1.f / l_i[i];
        int q = qt * 64 + ty + 16 * i;
        size_t base = (size_t)(b * S + q) * DM + h * DH + tx * 4;
        #pragma unroll
        for (int j = 0; j < 4; j++) {
            float v = acc[i][j] * inv;
            __nv_bfloat16 hi = __float2bfloat16(v);
            __nv_bfloat16 lo = __float2bfloat16(v - __bfloat162float(hi));
            g_zh[base + j] = hi;
            g_zl[base + j] = lo;
        }
    }
}

// ---------------------------------------------------------------------------
extern "C" void kernel_launch(void* const* d_in, const int* in_sizes, int n_in,
                              void* d_out, int out_size) {
    const float* x   = (const float*)d_in[0];
    const float* W_Q = (const float*)d_in[1];
    const float* W_K = (const float*)d_in[2];
    const float* W_V = (const float*)d_in[3];
    const float* W_O = (const float*)d_in[4];
    const float* b_Q = (const float*)d_in[5];
    const float* b_K = (const float*)d_in[6];
    const float* b_V = (const float*)d_in[7];
    const float* b_O = (const float*)d_in[8];
    float* out = (float*)d_out;

    // Pre-passes (only harness pointers cross host/device boundary)
    split_x_kernel<<<(MTOT * DM + 255) / 256, 256>>>(x);
    pack_wqkv_kernel<<<(NQKV * DM + 255) / 256, 256>>>(W_Q, W_K, W_V);
    pack_wo_kernel<<<(DM * DM + 255) / 256, 256>>>(W_O);

    // QKV projection: [4096,1024] x [3072,1024]^T
    {
        dim3 g(MTOT / 128, NQKV / 128);
        gemm_wmma<0><<<g, 256>>>(b_Q, b_K, b_V, b_O, out);
    }

    // Flash attention
    {
        dim3 g(S / 64, BH);
        attn_kernel<<<g, 256>>>();
    }

    // O projection: [4096,1024] x [1024,1024]^T
    {
        dim3 g(MTOT / 128, DM / 128);
        gemm_wmma<1><<<g, 256>>>(b_Q, b_K, b_V, b_O, out);
    }
}

// round 14
// speedup vs baseline: 1.7151x; 1.2301x over previous
#include <cuda_runtime.h>
#include <cuda_bf16.h>
#include <mma.h>
#include <stdint.h>

using namespace nvcuda;

// Problem constants
#define B      2
#define S      2048
#define DM     1024
#define H      16
#define DH     64
#define BH     (B*H)          // 32
#define MTOT   (B*S)          // 4096
#define NQKV   (3*DM)         // 3072
#define IGNORE_VAL (-1e5f)

// ---------------------------------------------------------------------------
// Global scratch. Referenced ONLY from device code (R11 lesson).
// ---------------------------------------------------------------------------
__device__ __align__(16) __nv_bfloat16 g_Qh[BH*S*DH];   // [bh][s][e] hi/lo
__device__ __align__(16) __nv_bfloat16 g_Ql[BH*S*DH];
__device__ __align__(16) __nv_bfloat16 g_Kh[BH*S*DH];
__device__ __align__(16) __nv_bfloat16 g_Kl[BH*S*DH];
__device__ __align__(16) __nv_bfloat16 g_Vh[BH*S*DH];
__device__ __align__(16) __nv_bfloat16 g_Vl[BH*S*DH];

__device__ __align__(16) __nv_bfloat16 g_xh[MTOT*DM];   // x split hi/lo, [m][k]
__device__ __align__(16) __nv_bfloat16 g_xl[MTOT*DM];
__device__ __align__(16) __nv_bfloat16 g_wqh[NQKV*DM];  // packed QKV W, [n][k]
__device__ __align__(16) __nv_bfloat16 g_wql[NQKV*DM];
__device__ __align__(16) __nv_bfloat16 g_woh[DM*DM];    // packed O W, [n][k]
__device__ __align__(16) __nv_bfloat16 g_wol[DM*DM];
__device__ __align__(16) __nv_bfloat16 g_zh[MTOT*DM];   // attn out, [m][h*64+e]
__device__ __align__(16) __nv_bfloat16 g_zl[MTOT*DM];

// ---------------------------------------------------------------------------
// Pre-passes
// ---------------------------------------------------------------------------
__global__ void split_x_kernel(const float* __restrict__ x) {
    int i = blockIdx.x * 256 + threadIdx.x;
    if (i < MTOT * DM) {
        float v = x[i];
        __nv_bfloat16 hi = __float2bfloat16(v);
        __nv_bfloat16 lo = __float2bfloat16(v - __bfloat162float(hi));
        g_xh[i] = hi; g_xl[i] = lo;
    }
}

__global__ void pack_wqkv_kernel(const float* __restrict__ Wq,
                                 const float* __restrict__ Wk,
                                 const float* __restrict__ Wv) {
    int i = blockIdx.x * 256 + threadIdx.x;
    if (i < NQKV * DM) {
        int n = i >> 10, k = i & 1023;
        int mat = n >> 10, h = (n >> 6) & 15, e = n & 63;
        const float* W = (mat == 0) ? Wq : (mat == 1 ? Wk : Wv);
        float v = W[(h * DM + k) * DH + e];
        __nv_bfloat16 hi = __float2bfloat16(v);
        __nv_bfloat16 lo = __float2bfloat16(v - __bfloat162float(hi));
        g_wqh[i] = hi; g_wql[i] = lo;
    }
}

__global__ void pack_wo_kernel(const float* __restrict__ Wo) {
    int i = blockIdx.x * 256 + threadIdx.x;
    if (i < DM * DM) {
        int n = i >> 10, k = i & 1023;
        float v = Wo[k * DM + n];
        __nv_bfloat16 hi = __float2bfloat16(v);
        __nv_bfloat16 lo = __float2bfloat16(v - __bfloat162float(hi));
        g_woh[i] = hi; g_wol[i] = lo;
    }
}

// ---------------------------------------------------------------------------
// WMMA GEMM (unchanged core from R13).
// MODE 0: qkv, epilogue splits to g_{Q,K,V}{h,l} bf16 + bias
// MODE 1: oproj, epilogue -> out + b_O
// ---------------------------------------------------------------------------
#define LDS_E  40
#define TILE_E (128*LDS_E)

template<int MODE>
__global__ void __launch_bounds__(256) gemm_wmma(
    const float* __restrict__ bq, const float* __restrict__ bk,
    const float* __restrict__ bv, const float* __restrict__ bo,
    float* __restrict__ out)
{
    __shared__ __align__(16) __nv_bfloat16 sAh[TILE_E];
    __shared__ __align__(16) __nv_bfloat16 sAl[TILE_E];
    __shared__ __align__(16) __nv_bfloat16 sBh[TILE_E];
    __shared__ __align__(16) __nv_bfloat16 sBl[TILE_E];

    const __nv_bfloat16* __restrict__ Ah = (MODE == 0) ? g_xh : g_zh;
    const __nv_bfloat16* __restrict__ Al = (MODE == 0) ? g_xl : g_zl;
    const __nv_bfloat16* __restrict__ Bh = (MODE == 0) ? g_wqh : g_woh;
    const __nv_bfloat16* __restrict__ Bl = (MODE == 0) ? g_wql : g_wol;

    const int tid = threadIdx.x;
    const int wid = tid >> 5;
    const int ln  = tid & 31;
    const int warpM = wid >> 1;
    const int warpN = wid & 1;
    const int m0 = blockIdx.x * 128;
    const int n0 = blockIdx.y * 128;

    wmma::fragment<wmma::accumulator, 16, 16, 16, float> c[2][4];
    #pragma unroll
    for (int mt = 0; mt < 2; mt++)
        #pragma unroll
        for (int nt = 0; nt < 4; nt++)
            wmma::fill_fragment(c[mt][nt], 0.0f);

    for (int ch = 0; ch < 32; ch++) {
        #pragma unroll
        for (int i = 0; i < 2; i++) {
            int idx = tid + i * 256;
            int row = idx >> 2, sl = idx & 3;
            int se = row * LDS_E + sl * 8;
            size_t ga = (size_t)(m0 + row) * DM + ch * 32 + sl * 8;
            size_t gb = (size_t)(n0 + row) * DM + ch * 32 + sl * 8;
            *(uint4*)(sAh + se) = *(const uint4*)(Ah + ga);
            *(uint4*)(sAl + se) = *(const uint4*)(Al + ga);
            *(uint4*)(sBh + se) = *(const uint4*)(Bh + gb);
            *(uint4*)(sBl + se) = *(const uint4*)(Bl + gb);
        }
        __syncthreads();

        #pragma unroll
        for (int kk = 0; kk < 2; kk++) {
            wmma::fragment<wmma::matrix_a, 16, 16, 16, __nv_bfloat16, wmma::row_major> aH[2], aL[2];
            wmma::fragment<wmma::matrix_b, 16, 16, 16, __nv_bfloat16, wmma::col_major> bH[4], bL[4];
            #pragma unroll
            for (int mt = 0; mt < 2; mt++) {
                int off = (warpM * 32 + mt * 16) * LDS_E + kk * 16;
                wmma::load_matrix_sync(aH[mt], sAh + off, LDS_E);
                wmma::load_matrix_sync(aL[mt], sAl + off, LDS_E);
            }
            #pragma unroll
            for (int nt = 0; nt < 4; nt++) {
                int off = (warpN * 64 + nt * 16) * LDS_E + kk * 16;
                wmma::load_matrix_sync(bH[nt], sBh + off, LDS_E);
                wmma::load_matrix_sync(bL[nt], sBl + off, LDS_E);
            }
            #pragma unroll
            for (int mt = 0; mt < 2; mt++) {
                #pragma unroll
                for (int nt = 0; nt < 4; nt++) {
                    wmma::mma_sync(c[mt][nt], aH[mt], bH[nt], c[mt][nt]);
                    wmma::mma_sync(c[mt][nt], aH[mt], bL[nt], c[mt][nt]);
                    wmma::mma_sync(c[mt][nt], aL[mt], bH[nt], c[mt][nt]);
                }
            }
        }
        __syncthreads();
    }

    float* stage = reinterpret_cast<float*>(sAh) + wid * 256;
    #pragma unroll
    for (int mt = 0; mt < 2; mt++) {
        #pragma unroll
        for (int nt = 0; nt < 4; nt++) {
            wmma::store_matrix_sync(stage, c[mt][nt], 16, wmma::mem_row_major);
            __syncwarp();
            int mb = m0 + warpM * 32 + mt * 16;
            int nb = n0 + warpN * 64 + nt * 16;
            #pragma unroll
            for (int j = 0; j < 8; j++) {
                int idx = ln * 8 + j;
                int r = idx >> 4, cc = idx & 15;
                int m = mb + r, n = nb + cc;
                float v = stage[idx];
                if (MODE == 0) {
                    int bb = m >> 11, s = m & 2047;
                    int mat = n >> 10, h = (n >> 6) & 15, e = n & 63;
                    const float* bias = (mat == 0) ? bq : (mat == 1 ? bk : bv);
                    v += bias[h * DH + e];
                    __nv_bfloat16 hi = __float2bfloat16(v);
                    __nv_bfloat16 lo = __float2bfloat16(v - __bfloat162float(hi));
                    size_t off = ((size_t)(bb * H + h) * S + s) * DH + e;
                    __nv_bfloat16* dh = (mat == 0) ? g_Qh : (mat == 1 ? g_Kh : g_Vh);
                    __nv_bfloat16* dl = (mat == 0) ? g_Ql : (mat == 1 ? g_Kl : g_Vl);
                    dh[off] = hi; dl[off] = lo;
                } else {
                    out[(size_t)m * DM + n] = v + bo[n];
                }
            }
            __syncwarp();
        }
    }
}

// ---------------------------------------------------------------------------
// Causal flash attention: wmma QK^T and P.V (3-term bf16 split), SIMT online
// softmax between them (R1-proven math). 64x64 tiles, 8 warps.
// Dynamic smem layout (bytes):
//  sQh 0   sQl 9216   sKh/Ph 18432   sKl/Pl 27648
//  sVh 36864   sVl 46080   sS(fp32) 55296   total 73728
// ---------------------------------------------------------------------------
#define LDA      72
#define ATT_SMEM 73728

__global__ void __launch_bounds__(256) attn_wmma() {
    extern __shared__ __align__(16) char smem_raw[];
    __nv_bfloat16* sQh = (__nv_bfloat16*)(smem_raw);
    __nv_bfloat16* sQl = (__nv_bfloat16*)(smem_raw + 9216);
    __nv_bfloat16* sKh = (__nv_bfloat16*)(smem_raw + 18432);  // doubles as Ph
    __nv_bfloat16* sKl = (__nv_bfloat16*)(smem_raw + 27648);  // doubles as Pl
    __nv_bfloat16* sVh = (__nv_bfloat16*)(smem_raw + 36864);
    __nv_bfloat16* sVl = (__nv_bfloat16*)(smem_raw + 46080);
    float*         sS  = (float*)(smem_raw + 55296);          // 64 x LDA fp32

    const int tid = threadIdx.x;
    const int wid = tid >> 5;
    const int tx  = tid & 15;
    const int ty  = tid >> 4;
    const int bh  = blockIdx.y;
    const int qt  = (int)gridDim.x - 1 - (int)blockIdx.x;

    const int mt  = wid >> 1;          // warp's m16 tile (0..3)
    const int n0t = (wid & 1) * 2;     // warp's first n16 tile (0 or 2)

    const __nv_bfloat16* Qhp = g_Qh + ((size_t)bh * S + qt * 64) * DH;
    const __nv_bfloat16* Qlp = g_Ql + ((size_t)bh * S + qt * 64) * DH;

    // load Q hi/lo (64x64 bf16, stride LDA)
    #pragma unroll
    for (int i = 0; i < 2; i++) {
        int idx = tid + i * 256;           // 0..511
        int row = idx >> 3, sl = idx & 7;
        int se = row * LDA + sl * 8;
        *(uint4*)(sQh + se) = *(const uint4*)(Qhp + row * 64 + sl * 8);
        *(uint4*)(sQl + se) = *(const uint4*)(Qlp + row * 64 + sl * 8);
    }

    float m_i[4], l_i[4], acc[4][4] = {};
    #pragma unroll
    for (int i = 0; i < 4; i++) { m_i[i] = -1e30f; l_i[i] = 0.f; }

    for (int kt = 0; kt <= qt; kt++) {
        const __nv_bfloat16* Khp = g_Kh + ((size_t)bh * S + kt * 64) * DH;
        const __nv_bfloat16* Klp = g_Kl + ((size_t)bh * S + kt * 64) * DH;
        const __nv_bfloat16* Vhp = g_Vh + ((size_t)bh * S + kt * 64) * DH;
        const __nv_bfloat16* Vlp = g_Vl + ((size_t)bh * S + kt * 64) * DH;
        #pragma unroll
        for (int i = 0; i < 2; i++) {
            int idx = tid + i * 256;
            int row = idx >> 3, sl = idx & 7;
            int se = row * LDA + sl * 8;
            int ge = row * 64 + sl * 8;
            *(uint4*)(sKh + se) = *(const uint4*)(Khp + ge);
            *(uint4*)(sKl + se) = *(const uint4*)(Klp + ge);
            *(uint4*)(sVh + se) = *(const uint4*)(Vhp + ge);
            *(uint4*)(sVl + se) = *(const uint4*)(Vlp + ge);
        }
        __syncthreads();

        // ---- S = Q K^T (3-term), fp32 accum -> sS ----
        {
            wmma::fragment<wmma::accumulator, 16, 16, 16, float> sacc[2];
            wmma::fill_fragment(sacc[0], 0.0f);
            wmma::fill_fragment(sacc[1], 0.0f);
            #pragma unroll
            for (int ks = 0; ks < 4; ks++) {
                wmma::fragment<wmma::matrix_a, 16, 16, 16, __nv_bfloat16, wmma::row_major> aH, aL;
                wmma::load_matrix_sync(aH, sQh + (mt * 16) * LDA + ks * 16, LDA);
                wmma::load_matrix_sync(aL, sQl + (mt * 16) * LDA + ks * 16, LDA);
                #pragma unroll
                for (int j = 0; j < 2; j++) {
                    wmma::fragment<wmma::matrix_b, 16, 16, 16, __nv_bfloat16, wmma::col_major> bH, bL;
                    wmma::load_matrix_sync(bH, sKh + ((n0t + j) * 16) * LDA + ks * 16, LDA);
                    wmma::load_matrix_sync(bL, sKl + ((n0t + j) * 16) * LDA + ks * 16, LDA);
                    wmma::mma_sync(sacc[j], aH, bH, sacc[j]);
                    wmma::mma_sync(sacc[j], aH, bL, sacc[j]);
                    wmma::mma_sync(sacc[j], aL, bH, sacc[j]);
                }
            }
            wmma::store_matrix_sync(sS + (mt * 16) * LDA + n0t * 16, sacc[0], LDA, wmma::mem_row_major);
            wmma::store_matrix_sync(sS + (mt * 16) * LDA + (n0t + 1) * 16, sacc[1], LDA, wmma::mem_row_major);
        }
        __syncthreads();

        // ---- SIMT online softmax on sS; P -> sKh/sKl (bf16 hi/lo) ----
        float sv[4][4];
        #pragma unroll
        for (int i = 0; i < 4; i++) {
            float4 v4 = *(const float4*)(sS + (ty + 16 * i) * LDA + tx * 4);
            sv[i][0] = v4.x * 0.125f; sv[i][1] = v4.y * 0.125f;
            sv[i][2] = v4.z * 0.125f; sv[i][3] = v4.w * 0.125f;
        }
        if (kt == qt) {
            #pragma unroll
            for (int i = 0; i < 4; i++)
                #pragma unroll
                for (int j = 0; j < 4; j++)
                    if (tx * 4 + j > ty + 16 * i) sv[i][j] = IGNORE_VAL;
        }

        float mx[4];
        #pragma unroll
        for (int i = 0; i < 4; i++)
            mx[i] = fmaxf(fmaxf(sv[i][0], sv[i][1]), fmaxf(sv[i][2], sv[i][3]));
        #pragma unroll
        for (int o = 8; o > 0; o >>= 1)
            #pragma unroll
            for (int i = 0; i < 4; i++)
                mx[i] = fmaxf(mx[i], __shfl_xor_sync(0xffffffffu, mx[i], o));

        float alpha[4];
        #pragma unroll
        for (int i = 0; i < 4; i++) {
            float mnew = fmaxf(m_i[i], mx[i]);
            alpha[i] = __expf(m_i[i] - mnew);
            m_i[i] = mnew;
        }
        #pragma unroll
        for (int i = 0; i < 4; i++)
            #pragma unroll
            for (int j = 0; j < 4; j++)
                sv[i][j] = __expf(sv[i][j] - m_i[i]);

        float rs[4];
        #pragma unroll
        for (int i = 0; i < 4; i++)
            rs[i] = (sv[i][0] + sv[i][1]) + (sv[i][2] + sv[i][3]);
        #pragma unroll
        for (int o = 8; o > 0; o >>= 1)
            #pragma unroll
            for (int i = 0; i < 4; i++)
                rs[i] += __shfl_xor_sync(0xffffffffu, rs[i], o);
        #pragma unroll
        for (int i = 0; i < 4; i++)
            l_i[i] = l_i[i] * alpha[i] + rs[i];

        // write P hi/lo over K buffers
        #pragma unroll
        for (int i = 0; i < 4; i++) {
            int off = (ty + 16 * i) * LDA + tx * 4;
            #pragma unroll
            for (int j = 0; j < 4; j++) {
                __nv_bfloat16 hi = __float2bfloat16(sv[i][j]);
                __nv_bfloat16 lo = __float2bfloat16(sv[i][j] - __bfloat162float(hi));
                sKh[off + j] = hi;
                sKl[off + j] = lo;
            }
        }
        __syncthreads();

        // ---- PV = P V (3-term) -> sS ----
        {
            wmma::fragment<wmma::accumulator, 16, 16, 16, float> pacc[2];
            wmma::fill_fragment(pacc[0], 0.0f);
            wmma::fill_fragment(pacc[1], 0.0f);
            #pragma unroll
            for (int ks = 0; ks < 4; ks++) {
                wmma::fragment<wmma::matrix_a, 16, 16, 16, __nv_bfloat16, wmma::row_major> pH, pL;
                wmma::load_matrix_sync(pH, sKh + (mt * 16) * LDA + ks * 16, LDA);
                wmma::load_matrix_sync(pL, sKl + (mt * 16) * LDA + ks * 16, LDA);
                #pragma unroll
                for (int j = 0; j < 2; j++) {
                    wmma::fragment<wmma::matrix_b, 16, 16, 16, __nv_bfloat16, wmma::row_major> vH, vL;
                    wmma::load_matrix_sync(vH, sVh + (ks * 16) * LDA + (n0t + j) * 16, LDA);
                    wmma::load_matrix_sync(vL, sVl + (ks * 16) * LDA + (n0t + j) * 16, LDA);
                    wmma::mma_sync(pacc[j], pH, vH, pacc[j]);
                    wmma::mma_sync(pacc[j], pH, vL, pacc[j]);
                    wmma::mma_sync(pacc[j], pL, vH, pacc[j]);
                }
            }
            wmma::store_matrix_sync(sS + (mt * 16) * LDA + n0t * 16, pacc[0], LDA, wmma::mem_row_major);
            wmma::store_matrix_sync(sS + (mt * 16) * LDA + (n0t + 1) * 16, pacc[1], LDA, wmma::mem_row_major);
        }
        __syncthreads();

        // ---- SIMT rescale + accumulate ----
        #pragma unroll
        for (int i = 0; i < 4; i++) {
            float4 v4 = *(const float4*)(sS + (ty + 16 * i) * LDA + tx * 4);
            acc[i][0] = acc[i][0] * alpha[i] + v4.x;
            acc[i][1] = acc[i][1] * alpha[i] + v4.y;
            acc[i][2] = acc[i][2] * alpha[i] + v4.z;
            acc[i][3] = acc[i][3] * alpha[i] + v4.w;
        }
        __syncthreads();   // before next tile overwrites K/V/S
    }

    // epilogue: Z -> bf16 hi/lo at [b*S+q][h*64+e]
    const int b = bh >> 4, h = bh & 15;
    #pragma unroll
    for (int i = 0; i < 4; i++) {
        float inv = 1.f / l_i[i];
        int q = qt * 64 + ty + 16 * i;
        size_t base = (size_t)(b * S + q) * DM + h * DH + tx * 4;
        #pragma unroll
        for (int j = 0; j < 4; j++) {
            float v = acc[i][j] * inv;
            __nv_bfloat16 hi = __float2bfloat16(v);
            __nv_bfloat16 lo = __float2bfloat16(v - __bfloat162float(hi));
            g_zh[base + j] = hi;
            g_zl[base + j] = lo;
        }
    }
}

// ---------------------------------------------------------------------------
extern "C" void kernel_launch(void* const* d_in, const int* in_sizes, int n_in,
                              void* d_out, int out_size) {
    const float* x   = (const float*)d_in[0];
    const float* W_Q = (const float*)d_in[1];
    const float* W_K = (const float*)d_in[2];
    const float* W_V = (const float*)d_in[3];
    const float* W_O = (const float*)d_in[4];
    const float* b_Q = (const float*)d_in[5];
    const float* b_K = (const float*)d_in[6];
    const float* b_V = (const float*)d_in[7];
    const float* b_O = (const float*)d_in[8];
    float* out = (float*)d_out;

    cudaFuncSetAttribute(attn_wmma, cudaFuncAttributeMaxDynamicSharedMemorySize, ATT_SMEM);

    // Pre-passes
    split_x_kernel<<<(MTOT * DM + 255) / 256, 256>>>(x);
    pack_wqkv_kernel<<<(NQKV * DM + 255) / 256, 256>>>(W_Q, W_K, W_V);
    pack_wo_kernel<<<(DM * DM + 255) / 256, 256>>>(W_O);

    // QKV projection
    {
        dim3 g(MTOT / 128, NQKV / 128);
        gemm_wmma<0><<<g, 256>>>(b_Q, b_K, b_V, b_O, out);
    }

    // Flash attention (wmma)
    {
        dim3 g(S / 64, BH);
        attn_wmma<<<g, 256, ATT_SMEM>>>();
    }

    // O projection
    {
        dim3 g(MTOT / 128, DM / 128);
        gemm_wmma<1><<<g, 256>>>(b_Q, b_K, b_V, b_O, out);
    }
}

// round 15
// speedup vs baseline: 1.9456x; 1.1344x over previous
#include <cuda_runtime.h>
#include <cuda_bf16.h>
#include <mma.h>
#include <stdint.h>

using namespace nvcuda;

// Problem constants
#define B      2
#define S      2048
#define DM     1024
#define H      16
#define DH     64
#define BH     (B*H)          // 32
#define MTOT   (B*S)          // 4096
#define NQKV   (3*DM)         // 3072
#define IGNORE_VAL (-1e5f)

// ---------------------------------------------------------------------------
// Global scratch. Referenced ONLY from device code (R11 lesson).
// ---------------------------------------------------------------------------
__device__ __align__(16) __nv_bfloat16 g_Qh[BH*S*DH];
__device__ __align__(16) __nv_bfloat16 g_Ql[BH*S*DH];
__device__ __align__(16) __nv_bfloat16 g_Kh[BH*S*DH];
__device__ __align__(16) __nv_bfloat16 g_Kl[BH*S*DH];
__device__ __align__(16) __nv_bfloat16 g_Vh[BH*S*DH];
__device__ __align__(16) __nv_bfloat16 g_Vl[BH*S*DH];

__device__ __align__(16) __nv_bfloat16 g_xh[MTOT*DM];
__device__ __align__(16) __nv_bfloat16 g_xl[MTOT*DM];
__device__ __align__(16) __nv_bfloat16 g_wqh[NQKV*DM];
__device__ __align__(16) __nv_bfloat16 g_wql[NQKV*DM];
__device__ __align__(16) __nv_bfloat16 g_woh[DM*DM];
__device__ __align__(16) __nv_bfloat16 g_wol[DM*DM];
__device__ __align__(16) __nv_bfloat16 g_zh[MTOT*DM];
__device__ __align__(16) __nv_bfloat16 g_zl[MTOT*DM];

// ---------------------------------------------------------------------------
// cp.async helpers (sm_80-era, valid on base sm_103)
// ---------------------------------------------------------------------------
__device__ __forceinline__ uint32_t smem_u32(const void* p) {
    uint32_t a;
    asm("{ .reg .u64 t; cvta.to.shared.u64 t, %1; cvt.u32.u64 %0, t; }" : "=r"(a) : "l"(p));
    return a;
}
__device__ __forceinline__ void cp_async16(uint32_t sa, const void* g) {
    asm volatile("cp.async.cg.shared.global [%0], [%1], 16;" :: "r"(sa), "l"(g));
}
__device__ __forceinline__ void cp_commit() {
    asm volatile("cp.async.commit_group;");
}
template<int N>
__device__ __forceinline__ void cp_wait() {
    asm volatile("cp.async.wait_group %0;" :: "n"(N));
}

// ---------------------------------------------------------------------------
// Pre-passes
// ---------------------------------------------------------------------------
__global__ void split_x_kernel(const float* __restrict__ x) {
    int i = blockIdx.x * 256 + threadIdx.x;
    if (i < MTOT * DM) {
        float v = x[i];
        __nv_bfloat16 hi = __float2bfloat16(v);
        __nv_bfloat16 lo = __float2bfloat16(v - __bfloat162float(hi));
        g_xh[i] = hi; g_xl[i] = lo;
    }
}

__global__ void pack_wqkv_kernel(const float* __restrict__ Wq,
                                 const float* __restrict__ Wk,
                                 const float* __restrict__ Wv) {
    int i = blockIdx.x * 256 + threadIdx.x;
    if (i < NQKV * DM) {
        int n = i >> 10, k = i & 1023;
        int mat = n >> 10, h = (n >> 6) & 15, e = n & 63;
        const float* W = (mat == 0) ? Wq : (mat == 1 ? Wk : Wv);
        float v = W[(h * DM + k) * DH + e];
        __nv_bfloat16 hi = __float2bfloat16(v);
        __nv_bfloat16 lo = __float2bfloat16(v - __bfloat162float(hi));
        g_wqh[i] = hi; g_wql[i] = lo;
    }
}

__global__ void pack_wo_kernel(const float* __restrict__ Wo) {
    int i = blockIdx.x * 256 + threadIdx.x;
    if (i < DM * DM) {
        int n = i >> 10, k = i & 1023;
        float v = Wo[k * DM + n];
        __nv_bfloat16 hi = __float2bfloat16(v);
        __nv_bfloat16 lo = __float2bfloat16(v - __bfloat162float(hi));
        g_woh[i] = hi; g_wol[i] = lo;
    }
}

// ---------------------------------------------------------------------------
// WMMA GEMM, 2-stage cp.async pipeline, K-chunk 64.
// Block 128x128, 8 warps (4Mx2N). Dynamic smem:
//   2 stages x 4 tiles x (128 rows x 72 bf16) = 147456 B.
// MODE 0: A=g_xh/xl, B=g_wqh/wql -> g_{Q,K,V}{h,l} + bias
// MODE 1: A=g_zh/zl, B=g_woh/wol -> out + b_O
// ---------------------------------------------------------------------------
#define LDS2    72
#define TILE2   (128*LDS2)        // 9216 elems = 18432 B per tile
#define STAGE2  (4*TILE2)         // elems per stage
#define GSMEM_B (2*STAGE2*2)      // 147456 bytes

template<int MODE>
__device__ __forceinline__ void gemm_prefetch(__nv_bfloat16* sm, int stg, int ch,
                                              int m0, int n0, int tid) {
    const __nv_bfloat16* Ah = (MODE == 0) ? g_xh : g_zh;
    const __nv_bfloat16* Al = (MODE == 0) ? g_xl : g_zl;
    const __nv_bfloat16* Bh = (MODE == 0) ? g_wqh : g_woh;
    const __nv_bfloat16* Bl = (MODE == 0) ? g_wql : g_wol;
    __nv_bfloat16* base = sm + stg * STAGE2;
    #pragma unroll
    for (int i = 0; i < 4; i++) {
        int idx = tid + i * 256;           // 0..1023
        int row = idx >> 3, sl = idx & 7;  // 8x 16B per 64-elem row
        uint32_t soff = (uint32_t)(row * LDS2 + sl * 8);
        size_t ga = (size_t)(m0 + row) * DM + ch * 64 + sl * 8;
        size_t gb = (size_t)(n0 + row) * DM + ch * 64 + sl * 8;
        cp_async16(smem_u32(base + 0 * TILE2 + soff), Ah + ga);
        cp_async16(smem_u32(base + 1 * TILE2 + soff), Al + ga);
        cp_async16(smem_u32(base + 2 * TILE2 + soff), Bh + gb);
        cp_async16(smem_u32(base + 3 * TILE2 + soff), Bl + gb);
    }
}

template<int MODE>
__global__ void __launch_bounds__(256) gemm_wmma(
    const float* __restrict__ bq, const float* __restrict__ bk,
    const float* __restrict__ bv, const float* __restrict__ bo,
    float* __restrict__ out)
{
    extern __shared__ __align__(16) __nv_bfloat16 sm[];

    const int tid = threadIdx.x;
    const int wid = tid >> 5;
    const int ln  = tid & 31;
    const int warpM = wid >> 1;
    const int warpN = wid & 1;
    const int m0 = blockIdx.x * 128;
    const int n0 = blockIdx.y * 128;

    wmma::fragment<wmma::accumulator, 16, 16, 16, float> c[2][4];
    #pragma unroll
    for (int mt = 0; mt < 2; mt++)
        #pragma unroll
        for (int nt = 0; nt < 4; nt++)
            wmma::fill_fragment(c[mt][nt], 0.0f);

    gemm_prefetch<MODE>(sm, 0, 0, m0, n0, tid);
    cp_commit();

    for (int ch = 0; ch < 16; ch++) {      // 16 chunks of K=64
        if (ch + 1 < 16) {
            gemm_prefetch<MODE>(sm, (ch + 1) & 1, ch + 1, m0, n0, tid);
            cp_commit();
            cp_wait<1>();
        } else {
            cp_wait<0>();
        }
        __syncthreads();

        __nv_bfloat16* st = sm + (ch & 1) * STAGE2;
        __nv_bfloat16* sAh = st;
        __nv_bfloat16* sAl = st + TILE2;
        __nv_bfloat16* sBh = st + 2 * TILE2;
        __nv_bfloat16* sBl = st + 3 * TILE2;

        #pragma unroll
        for (int kk = 0; kk < 4; kk++) {   // 4 k16 steps per chunk
            wmma::fragment<wmma::matrix_a, 16, 16, 16, __nv_bfloat16, wmma::row_major> aH[2], aL[2];
            #pragma unroll
            for (int mt = 0; mt < 2; mt++) {
                int off = (warpM * 32 + mt * 16) * LDS2 + kk * 16;
                wmma::load_matrix_sync(aH[mt], sAh + off, LDS2);
                wmma::load_matrix_sync(aL[mt], sAl + off, LDS2);
            }
            #pragma unroll
            for (int nt = 0; nt < 4; nt++) {   // b frags loaded per-nt (reg relief)
                wmma::fragment<wmma::matrix_b, 16, 16, 16, __nv_bfloat16, wmma::col_major> bH, bL;
                int off = (warpN * 64 + nt * 16) * LDS2 + kk * 16;
                wmma::load_matrix_sync(bH, sBh + off, LDS2);
                wmma::load_matrix_sync(bL, sBl + off, LDS2);
                #pragma unroll
                for (int mt = 0; mt < 2; mt++) {
                    wmma::mma_sync(c[mt][nt], aH[mt], bH, c[mt][nt]);
                    wmma::mma_sync(c[mt][nt], aH[mt], bL, c[mt][nt]);
                    wmma::mma_sync(c[mt][nt], aL[mt], bH, c[mt][nt]);
                }
            }
        }
        __syncthreads();
    }

    // ---- epilogue: stage each 16x16 C tile through per-warp smem ----
    float* stage = reinterpret_cast<float*>(sm) + wid * 256;
    #pragma unroll
    for (int mt = 0; mt < 2; mt++) {
        #pragma unroll
        for (int nt = 0; nt < 4; nt++) {
            wmma::store_matrix_sync(stage, c[mt][nt], 16, wmma::mem_row_major);
            __syncwarp();
            int mb = m0 + warpM * 32 + mt * 16;
            int nb = n0 + warpN * 64 + nt * 16;
            #pragma unroll
            for (int j = 0; j < 8; j++) {
                int idx = ln * 8 + j;
                int r = idx >> 4, cc = idx & 15;
                int m = mb + r, n = nb + cc;
                float v = stage[idx];
                if (MODE == 0) {
                    int bb = m >> 11, s = m & 2047;
                    int mat = n >> 10, h = (n >> 6) & 15, e = n & 63;
                    const float* bias = (mat == 0) ? bq : (mat == 1 ? bk : bv);
                    v += bias[h * DH + e];
                    __nv_bfloat16 hi = __float2bfloat16(v);
                    __nv_bfloat16 lo = __float2bfloat16(v - __bfloat162float(hi));
                    size_t off = ((size_t)(bb * H + h) * S + s) * DH + e;
                    __nv_bfloat16* dh = (mat == 0) ? g_Qh : (mat == 1 ? g_Kh : g_Vh);
                    __nv_bfloat16* dl = (mat == 0) ? g_Ql : (mat == 1 ? g_Kl : g_Vl);
                    dh[off] = hi; dl[off] = lo;
                } else {
                    out[(size_t)m * DM + n] = v + bo[n];
                }
            }
            __syncwarp();
        }
    }
}

// ---------------------------------------------------------------------------
// Causal flash attention: wmma QK^T and P.V, SIMT online softmax (R14, proven).
// ---------------------------------------------------------------------------
#define LDA      72
#define ATT_SMEM 73728

__global__ void __launch_bounds__(256) attn_wmma() {
    extern __shared__ __align__(16) char smem_raw[];
    __nv_bfloat16* sQh = (__nv_bfloat16*)(smem_raw);
    __nv_bfloat16* sQl = (__nv_bfloat16*)(smem_raw + 9216);
    __nv_bfloat16* sKh = (__nv_bfloat16*)(smem_raw + 18432);
    __nv_bfloat16* sKl = (__nv_bfloat16*)(smem_raw + 27648);
    __nv_bfloat16* sVh = (__nv_bfloat16*)(smem_raw + 36864);
    __nv_bfloat16* sVl = (__nv_bfloat16*)(smem_raw + 46080);
    float*         sS  = (float*)(smem_raw + 55296);

    const int tid = threadIdx.x;
    const int wid = tid >> 5;
    const int tx  = tid & 15;
    const int ty  = tid >> 4;
    const int bh  = blockIdx.y;
    const int qt  = (int)gridDim.x - 1 - (int)blockIdx.x;

    const int mt  = wid >> 1;
    const int n0t = (wid & 1) * 2;

    const __nv_bfloat16* Qhp = g_Qh + ((size_t)bh * S + qt * 64) * DH;
    const __nv_bfloat16* Qlp = g_Ql + ((size_t)bh * S + qt * 64) * DH;

    #pragma unroll
    for (int i = 0; i < 2; i++) {
        int idx = tid + i * 256;
        int row = idx >> 3, sl = idx & 7;
        int se = row * LDA + sl * 8;
        *(uint4*)(sQh + se) = *(const uint4*)(Qhp + row * 64 + sl * 8);
        *(uint4*)(sQl + se) = *(const uint4*)(Qlp + row * 64 + sl * 8);
    }

    float m_i[4], l_i[4], acc[4][4] = {};
    #pragma unroll
    for (int i = 0; i < 4; i++) { m_i[i] = -1e30f; l_i[i] = 0.f; }

    for (int kt = 0; kt <= qt; kt++) {
        const __nv_bfloat16* Khp = g_Kh + ((size_t)bh * S + kt * 64) * DH;
        const __nv_bfloat16* Klp = g_Kl + ((size_t)bh * S + kt * 64) * DH;
        const __nv_bfloat16* Vhp = g_Vh + ((size_t)bh * S + kt * 64) * DH;
        const __nv_bfloat16* Vlp = g_Vl + ((size_t)bh * S + kt * 64) * DH;
        #pragma unroll
        for (int i = 0; i < 2; i++) {
            int idx = tid + i * 256;
            int row = idx >> 3, sl = idx & 7;
            int se = row * LDA + sl * 8;
            int ge = row * 64 + sl * 8;
            *(uint4*)(sKh + se) = *(const uint4*)(Khp + ge);
            *(uint4*)(sKl + se) = *(const uint4*)(Klp + ge);
            *(uint4*)(sVh + se) = *(const uint4*)(Vhp + ge);
            *(uint4*)(sVl + se) = *(const uint4*)(Vlp + ge);
        }
        __syncthreads();

        {
            wmma::fragment<wmma::accumulator, 16, 16, 16, float> sacc[2];
            wmma::fill_fragment(sacc[0], 0.0f);
            wmma::fill_fragment(sacc[1], 0.0f);
            #pragma unroll
            for (int ks = 0; ks < 4; ks++) {
                wmma::fragment<wmma::matrix_a, 16, 16, 16, __nv_bfloat16, wmma::row_major> aH, aL;
                wmma::load_matrix_sync(aH, sQh + (mt * 16) * LDA + ks * 16, LDA);
                wmma::load_matrix_sync(aL, sQl + (mt * 16) * LDA + ks * 16, LDA);
                #pragma unroll
                for (int j = 0; j < 2; j++) {
                    wmma::fragment<wmma::matrix_b, 16, 16, 16, __nv_bfloat16, wmma::col_major> bH, bL;
                    wmma::load_matrix_sync(bH, sKh + ((n0t + j) * 16) * LDA + ks * 16, LDA);
                    wmma::load_matrix_sync(bL, sKl + ((n0t + j) * 16) * LDA + ks * 16, LDA);
                    wmma::mma_sync(sacc[j], aH, bH, sacc[j]);
                    wmma::mma_sync(sacc[j], aH, bL, sacc[j]);
                    wmma::mma_sync(sacc[j], aL, bH, sacc[j]);
                }
            }
            wmma::store_matrix_sync(sS + (mt * 16) * LDA + n0t * 16, sacc[0], LDA, wmma::mem_row_major);
            wmma::store_matrix_sync(sS + (mt * 16) * LDA + (n0t + 1) * 16, sacc[1], LDA, wmma::mem_row_major);
        }
        __syncthreads();

        float sv[4][4];
        #pragma unroll
        for (int i = 0; i < 4; i++) {
            float4 v4 = *(const float4*)(sS + (ty + 16 * i) * LDA + tx * 4);
            sv[i][0] = v4.x * 0.125f; sv[i][1] = v4.y * 0.125f;
            sv[i][2] = v4.z * 0.125f; sv[i][3] = v4.w * 0.125f;
        }
        if (kt == qt) {
            #pragma unroll
            for (int i = 0; i < 4; i++)
                #pragma unroll
                for (int j = 0; j < 4; j++)
                    if (tx * 4 + j > ty + 16 * i) sv[i][j] = IGNORE_VAL;
        }

        float mx[4];
        #pragma unroll
        for (int i = 0; i < 4; i++)
            mx[i] = fmaxf(fmaxf(sv[i][0], sv[i][1]), fmaxf(sv[i][2], sv[i][3]));
        #pragma unroll
        for (int o = 8; o > 0; o >>= 1)
            #pragma unroll
            for (int i = 0; i < 4; i++)
                mx[i] = fmaxf(mx[i], __shfl_xor_sync(0xffffffffu, mx[i], o));

        float alpha[4];
        #pragma unroll
        for (int i = 0; i < 4; i++) {
            float mnew = fmaxf(m_i[i], mx[i]);
            alpha[i] = __expf(m_i[i] - mnew);
            m_i[i] = mnew;
        }
        #pragma unroll
        for (int i = 0; i < 4; i++)
            #pragma unroll
            for (int j = 0; j < 4; j++)
                sv[i][j] = __expf(sv[i][j] - m_i[i]);

        float rs[4];
        #pragma unroll
        for (int i = 0; i < 4; i++)
            rs[i] = (sv[i][0] + sv[i][1]) + (sv[i][2] + sv[i][3]);
        #pragma unroll
        for (int o = 8; o > 0; o >>= 1)
            #pragma unroll
            for (int i = 0; i < 4; i++)
                rs[i] += __shfl_xor_sync(0xffffffffu, rs[i], o);
        #pragma unroll
        for (int i = 0; i < 4; i++)
            l_i[i] = l_i[i] * alpha[i] + rs[i];

        #pragma unroll
        for (int i = 0; i < 4; i++) {
            int off = (ty + 16 * i) * LDA + tx * 4;
            #pragma unroll
            for (int j = 0; j < 4; j++) {
                __nv_bfloat16 hi = __float2bfloat16(sv[i][j]);
                __nv_bfloat16 lo = __float2bfloat16(sv[i][j] - __bfloat162float(hi));
                sKh[off + j] = hi;
                sKl[off + j] = lo;
            }
        }
        __syncthreads();

        {
            wmma::fragment<wmma::accumulator, 16, 16, 16, float> pacc[2];
            wmma::fill_fragment(pacc[0], 0.0f);
            wmma::fill_fragment(pacc[1], 0.0f);
            #pragma unroll
            for (int ks = 0; ks < 4; ks++) {
                wmma::fragment<wmma::matrix_a, 16, 16, 16, __nv_bfloat16, wmma::row_major> pH, pL;
                wmma::load_matrix_sync(pH, sKh + (mt * 16) * LDA + ks * 16, LDA);
                wmma::load_matrix_sync(pL, sKl + (mt * 16) * LDA + ks * 16, LDA);
                #pragma unroll
                for (int j = 0; j < 2; j++) {
                    wmma::fragment<wmma::matrix_b, 16, 16, 16, __nv_bfloat16, wmma::row_major> vH, vL;
                    wmma::load_matrix_sync(vH, sVh + (ks * 16) * LDA + (n0t + j) * 16, LDA);
                    wmma::load_matrix_sync(vL, sVl + (ks * 16) * LDA + (n0t + j) * 16, LDA);
                    wmma::mma_sync(pacc[j], pH, vH, pacc[j]);
                    wmma::mma_sync(pacc[j], pH, vL, pacc[j]);
                    wmma::mma_sync(pacc[j], pL, vH, pacc[j]);
                }
            }
            wmma::store_matrix_sync(sS + (mt * 16) * LDA + n0t * 16, pacc[0], LDA, wmma::mem_row_major);
            wmma::store_matrix_sync(sS + (mt * 16) * LDA + (n0t + 1) * 16, pacc[1], LDA, wmma::mem_row_major);
        }
        __syncthreads();

        #pragma unroll
        for (int i = 0; i < 4; i++) {
            float4 v4 = *(const float4*)(sS + (ty + 16 * i) * LDA + tx * 4);
            acc[i][0] = acc[i][0] * alpha[i] + v4.x;
            acc[i][1] = acc[i][1] * alpha[i] + v4.y;
            acc[i][2] = acc[i][2] * alpha[i] + v4.z;
            acc[i][3] = acc[i][3] * alpha[i] + v4.w;
        }
        __syncthreads();
    }

    const int b = bh >> 4, h = bh & 15;
    #pragma unroll
    for (int i = 0; i < 4; i++) {
        float inv = 1.f / l_i[i];
        int q = qt * 64 + ty + 16 * i;
        size_t base = (size_t)(b * S + q) * DM + h * DH + tx * 4;
        #pragma unroll
        for (int j = 0; j < 4; j++) {
            float v = acc[i][j] * inv;
            __nv_bfloat16 hi = __float2bfloat16(v);
            __nv_bfloat16 lo = __float2bfloat16(v - __bfloat162float(hi));
            g_zh[base + j] = hi;
            g_zl[base + j] = lo;
        }
    }
}

// ---------------------------------------------------------------------------
extern "C" void kernel_launch(void* const* d_in, const int* in_sizes, int n_in,
                              void* d_out, int out_size) {
    const float* x   = (const float*)d_in[0];
    const float* W_Q = (const float*)d_in[1];
    const float* W_K = (const float*)d_in[2];
    const float* W_V = (const float*)d_in[3];
    const float* W_O = (const float*)d_in[4];
    const float* b_Q = (const float*)d_in[5];
    const float* b_K = (const float*)d_in[6];
    const float* b_V = (const float*)d_in[7];
    const float* b_O = (const float*)d_in[8];
    float* out = (float*)d_out;

    cudaFuncSetAttribute(attn_wmma, cudaFuncAttributeMaxDynamicSharedMemorySize, ATT_SMEM);
    cudaFuncSetAttribute(gemm_wmma<0>, cudaFuncAttributeMaxDynamicSharedMemorySize, GSMEM_B);
    cudaFuncSetAttribute(gemm_wmma<1>, cudaFuncAttributeMaxDynamicSharedMemorySize, GSMEM_B);

    // Pre-passes
    split_x_kernel<<<(MTOT * DM + 255) / 256, 256>>>(x);
    pack_wqkv_kernel<<<(NQKV * DM + 255) / 256, 256>>>(W_Q, W_K, W_V);
    pack_wo_kernel<<<(DM * DM + 255) / 256, 256>>>(W_O);

    // QKV projection
    {
        dim3 g(MTOT / 128, NQKV / 128);
        gemm_wmma<0><<<g, 256, GSMEM_B>>>(b_Q, b_K, b_V, b_O, out);
    }

    // Flash attention (wmma)
    {
        dim3 g(S / 64, BH);
        attn_wmma<<<g, 256, ATT_SMEM>>>();
    }

    // O projection
    {
        dim3 g(MTOT / 128, DM / 128);
        gemm_wmma<1><<<g, 256, GSMEM_B>>>(b_Q, b_K, b_V, b_O, out);
    }
}